// round 11
// baseline (speedup 1.0000x reference)
#include <cuda_runtime.h>
#include <cuda_fp16.h>
#include <math_constants.h>

#define NN 50000
#define EE 800000
#define ETOT (EE + NN)
#define HC 128
#define FF 64
#define FULLMASK 0xffffffffu
#define NB 49     // ceil(NN/1024)
#define NBLK 148  // one block per SM -> co-resident

// ---------------- device scratch (static, no allocs) ----------------
__device__ int g_deg[NN];
__device__ int g_cur[NN];
__device__ int g_off[NN + 1];
__device__ int g_bsum[64];
__device__ int g_bars[4];
__device__ int g_srcs[ETOT];                // stores src<<7 (row element offset)
__device__ float g_xl32[(size_t)NN * HC];   // fp32, quad-interleaved (layer 1)
__device__ __half g_xl16[(size_t)NN * HC];  // fp16 gathered operand (layers 2,3)
__device__ float g_xr[(size_t)NN * HC];
__device__ float g_y[(size_t)NN * FF];
__device__ float g_stats[3][2 * FF];

// ---------------- zero (deg + stats + barriers) ----------------
__global__ void k_zero() {
    int i = blockIdx.x * blockDim.x + threadIdx.x;
    if (i < NN) g_deg[i] = 0;
    if (i < 3 * 2 * FF) ((float*)g_stats)[i] = 0.f;
    if (i < 4) g_bars[i] = 0;
}

// ---------------- persistent CSR kernel: hist + scan + scatter ----------------
__device__ __forceinline__ void gridbar(int k) {
    __threadfence();
    __syncthreads();
    if (threadIdx.x == 0) {
        atomicAdd(&g_bars[k], 1);
        while (*(volatile int*)&g_bars[k] < NBLK) { }
    }
    __syncthreads();
}

__global__ __launch_bounds__(1024) void k_csrall(const int* __restrict__ ei) {
    __shared__ int wsum[32];
    __shared__ int sh[64];
    int tid = threadIdx.x;
    int lane = tid & 31, wid = tid >> 5;
    int gtid = blockIdx.x * 1024 + tid;
    const int nthreads = NBLK * 1024;

    // P1: degree histogram (int4-vectorized)
    for (int t = gtid; t < EE / 4; t += nthreads) {
        int4 d4 = ((const int4*)(ei + EE))[t];
        atomicAdd(&g_deg[d4.x], 1);
        atomicAdd(&g_deg[d4.y], 1);
        atomicAdd(&g_deg[d4.z], 1);
        atomicAdd(&g_deg[d4.w], 1);
    }
    gridbar(0);

    // P2: per-1024-tile local inclusive scan (blocks 0..NB-1)
    int incl = 0, v = 0;
    int gi = blockIdx.x * 1024 + tid;
    if (blockIdx.x < NB) {
        v = (gi < NN) ? (g_deg[gi] + 1) : 0;  // +1 = self-loop
        int s = v;
#pragma unroll
        for (int d = 1; d < 32; d <<= 1) {
            int t = __shfl_up_sync(FULLMASK, s, d);
            if (lane >= d) s += t;
        }
        if (lane == 31) wsum[wid] = s;
        __syncthreads();
        if (wid == 0) {
            int w = wsum[lane];
#pragma unroll
            for (int d = 1; d < 32; d <<= 1) {
                int t = __shfl_up_sync(FULLMASK, w, d);
                if (lane >= d) w += t;
            }
            wsum[lane] = w;
        }
        __syncthreads();
        incl = s + (wid ? wsum[wid - 1] : 0);
        if (tid == 1023) g_bsum[blockIdx.x] = incl;
    }
    gridbar(1);

    // P3: every tile-block scans the NB block sums itself, then fixes its tile
    if (blockIdx.x < NB) {
        if (tid < 64) sh[tid] = (tid < NB) ? __ldcg(&g_bsum[tid]) : 0;
        __syncthreads();
        if (tid < 32) {
            int sa = sh[tid];
#pragma unroll
            for (int d = 1; d < 32; d <<= 1) {
                int t = __shfl_up_sync(FULLMASK, sa, d);
                if (lane >= d) sa += t;
            }
            int ta = __shfl_sync(FULLMASK, sa, 31);
            int sb = sh[tid + 32];
#pragma unroll
            for (int d = 1; d < 32; d <<= 1) {
                int t = __shfl_up_sync(FULLMASK, sb, d);
                if (lane >= d) sb += t;
            }
            sh[tid] = sa;
            sh[tid + 32] = sb + ta;
        }
        __syncthreads();
        int pre = blockIdx.x ? sh[blockIdx.x - 1] : 0;
        if (gi < NN) {
            int off = incl + pre;
            g_off[gi + 1] = off;
            g_cur[gi] = off - v;
        }
        if (gi == 0) g_off[0] = 0;
    }
    gridbar(2);

    // P4: scatter (int4-vectorized edges + self-loop tail); store src<<7
    for (int t = gtid; t < EE / 4 + NN; t += nthreads) {
        if (t < EE / 4) {
            int4 s4 = ((const int4*)ei)[t];
            int4 d4 = ((const int4*)(ei + EE))[t];
            g_srcs[atomicAdd(&g_cur[d4.x], 1)] = s4.x << 7;
            g_srcs[atomicAdd(&g_cur[d4.y], 1)] = s4.y << 7;
            g_srcs[atomicAdd(&g_cur[d4.z], 1)] = s4.z << 7;
            g_srcs[atomicAdd(&g_cur[d4.w], 1)] = s4.w << 7;
        } else {
            int n = t - EE / 4;
            g_srcs[atomicAdd(&g_cur[n], 1)] = n << 7;
        }
    }
}

// ---------------- GEMM layer 1 (K=3): xl->fp32 quad-interleaved, xr->fp32 ----------------
__global__ void k_gemmA(const float* __restrict__ X,
                        const float* __restrict__ Wl,
                        const float* __restrict__ Wr) {
    __shared__ float sW[3][HC];
    __shared__ float sX[64][3];
    const float* W = (blockIdx.y == 0) ? Wl : Wr;
    int tid = threadIdx.x;
    int row0 = blockIdx.x * 64;

    for (int idx = tid; idx < 3 * HC; idx += 256)
        sW[idx / HC][idx % HC] = W[idx];
    for (int idx = tid; idx < 64 * 3; idx += 256) {
        int r = idx / 3, k = idx % 3;
        sX[r][k] = (row0 + r < NN) ? X[(size_t)(row0 + r) * 3 + k] : 0.f;
    }
    __syncthreads();

    int tx = tid & 31, ty = tid >> 5;
    float4 acc[8];
#pragma unroll
    for (int i = 0; i < 8; i++) acc[i] = make_float4(0.f, 0.f, 0.f, 0.f);
#pragma unroll
    for (int k = 0; k < 3; k++) {
        float4 b = *(const float4*)&sW[k][tx * 4];
#pragma unroll
        for (int i = 0; i < 8; i++) {
            float a = sX[ty * 8 + i][k];
            acc[i].x += a * b.x;
            acc[i].y += a * b.y;
            acc[i].z += a * b.z;
            acc[i].w += a * b.w;
        }
    }
    int scol = (blockIdx.y == 0) ? ((tx & 1) * 64 + (tx >> 1) * 4) : (tx * 4);
    float* out = (blockIdx.y == 0) ? g_xl32 : g_xr;
#pragma unroll
    for (int i = 0; i < 8; i++) {
        int r = row0 + ty * 8 + i;
        if (r < NN) *(float4*)&out[(size_t)r * HC + scol] = acc[i];
    }
}

// ---------------- GEMM layers 2,3 (K=64): xl->fp16, xr->fp32, fused norm+relu ----------------
#define SXIDX(k, r) (((k) << 6) + ((((((r) >> 1) ^ ((k) & 31))) << 1) | ((r) & 1)))

__global__ __launch_bounds__(256) void k_gemmB(
    const float* __restrict__ Wl, const float* __restrict__ Wr,
    const float* __restrict__ st, const float* __restrict__ gw,
    const float* __restrict__ gb, const float* __restrict__ gm) {
    __shared__ float sW[64 * HC];
    __shared__ float sX[64 * 64];
    __shared__ float sA[64], sB[64];
    int tid = threadIdx.x;
    const float* W = (blockIdx.y == 0) ? Wl : Wr;
    int row0 = blockIdx.x * 64;

    if (tid < 64) {
        const float invN = 1.f / (float)NN;
        float mu = st[tid] * invN;
        float ey2 = st[FF + tid] * invN;
        float gmc = gm[tid];
        float var = ey2 - 2.f * gmc * mu * mu + gmc * gmc * mu * mu;
        float al = gw[tid] * rsqrtf(var + 1e-5f);
        sA[tid] = al;
        sB[tid] = gb[tid] - al * gmc * mu;
    }
    for (int idx = tid; idx < 64 * HC; idx += 256) sW[idx] = W[idx];
    __syncthreads();
    for (int idx = tid; idx < 64 * 64; idx += 256) {
        int r = idx >> 6, k = idx & 63;
        float v = 0.f;
        if (row0 + r < NN) {
            float y = g_y[(size_t)(row0 + r) * FF + k];
            v = fmaxf(sA[k] * y + sB[k], 0.f);
        }
        sX[SXIDX(k, r)] = v;
    }
    __syncthreads();

    int tx = tid & 31, ty = tid >> 5;
    unsigned long long acc[4][4];
#pragma unroll
    for (int i = 0; i < 4; i++)
#pragma unroll
        for (int c = 0; c < 4; c++) acc[i][c] = 0ull;

#pragma unroll 4
    for (int k = 0; k < 64; k++) {
        float4 b4 = *(const float4*)&sW[k * HC + tx * 4];
        unsigned long long bs0, bs1, bs2, bs3;
        asm("mov.b64 %0, {%1,%1};" : "=l"(bs0) : "f"(b4.x));
        asm("mov.b64 %0, {%1,%1};" : "=l"(bs1) : "f"(b4.y));
        asm("mov.b64 %0, {%1,%1};" : "=l"(bs2) : "f"(b4.z));
        asm("mov.b64 %0, {%1,%1};" : "=l"(bs3) : "f"(b4.w));
#pragma unroll
        for (int i = 0; i < 4; i++) {
            unsigned long long a =
                *(const unsigned long long*)&sX[SXIDX(k, ty * 8 + 2 * i)];
            asm("fma.rn.f32x2 %0, %1, %2, %0;" : "+l"(acc[i][0]) : "l"(a), "l"(bs0));
            asm("fma.rn.f32x2 %0, %1, %2, %0;" : "+l"(acc[i][1]) : "l"(a), "l"(bs1));
            asm("fma.rn.f32x2 %0, %1, %2, %0;" : "+l"(acc[i][2]) : "l"(a), "l"(bs2));
            asm("fma.rn.f32x2 %0, %1, %2, %0;" : "+l"(acc[i][3]) : "l"(a), "l"(bs3));
        }
    }

#pragma unroll
    for (int i = 0; i < 4; i++) {
        int r = row0 + ty * 8 + 2 * i;
        float lo[4], hi[4];
#pragma unroll
        for (int c = 0; c < 4; c++)
            asm("mov.b64 {%0,%1}, %2;" : "=f"(lo[c]), "=f"(hi[c]) : "l"(acc[i][c]));
        if (blockIdx.y == 0) {
            if (r < NN) {
                *(__half2*)&g_xl16[(size_t)r * HC + tx * 4] = __floats2half2_rn(lo[0], lo[1]);
                *(__half2*)&g_xl16[(size_t)r * HC + tx * 4 + 2] = __floats2half2_rn(lo[2], lo[3]);
            }
            if (r + 1 < NN) {
                *(__half2*)&g_xl16[(size_t)(r + 1) * HC + tx * 4] = __floats2half2_rn(hi[0], hi[1]);
                *(__half2*)&g_xl16[(size_t)(r + 1) * HC + tx * 4 + 2] = __floats2half2_rn(hi[2], hi[3]);
            }
        } else {
            if (r < NN)
                *(float4*)&g_xr[(size_t)r * HC + tx * 4] = make_float4(lo[0], lo[1], lo[2], lo[3]);
            if (r + 1 < NN)
                *(float4*)&g_xr[(size_t)(r + 1) * HC + tx * 4] = make_float4(hi[0], hi[1], hi[2], hi[3]);
        }
    }
}

// ---------------- edge kernel: warp per node, 2 edges/iter, unroll 1, high occupancy ----------------
__device__ __forceinline__ float ex2(float x) {
    float r;
    asm("ex2.approx.f32 %0, %1;" : "=f"(r) : "f"(x));
    return r;
}

template <bool HALFXL>
__global__ __launch_bounds__(512, 3) void k_edge(const float* __restrict__ att,
                                                 const float* __restrict__ bias,
                                                 float* __restrict__ st) {
    __shared__ float sS[2 * FF];
    int tid = threadIdx.x;
    if (tid < 2 * FF) sS[tid] = 0.f;
    __syncthreads();

    int warp = tid >> 5;
    int lane = tid & 31;
    int v = blockIdx.x * 16 + warp;
    int half = lane >> 4;
    int l16 = lane & 15;
    int ch0 = l16 * 8;

    const float LOG2E = 1.4426950408889634f;
    float4 attA = *(const float4*)&att[ch0];
    float4 attB = *(const float4*)&att[ch0 + 4];
    attA.x *= LOG2E; attA.y *= LOG2E; attA.z *= LOG2E; attA.w *= LOG2E;
    attB.x *= LOG2E; attB.y *= LOG2E; attB.z *= LOG2E; attB.w *= LOG2E;
    float4 xrA = *(const float4*)&g_xr[(size_t)v * HC + ch0];
    float4 xrB = *(const float4*)&g_xr[(size_t)v * HC + ch0 + 4];

    float z = 0.f;
    float4 accA = make_float4(0.f, 0.f, 0.f, 0.f);
    float4 accB = make_float4(0.f, 0.f, 0.f, 0.f);

    int beg = g_off[v], end = g_off[v + 1];
    for (int base = beg; base < end; base += 32) {
        int idx = base + lane;
        int sb = (idx < end) ? g_srcs[idx] : 0;  // src<<7
        int cnt = min(32, end - base);
        int pairs = (cnt + 1) >> 1;
        for (int t = 0; t < pairs; t++) {
            int eidx = 2 * t + half;
            bool valid = eidx < cnt;
            int soff = __shfl_sync(FULLMASK, sb, eidx);
            float4 xa, xb;
            if (HALFXL) {
                uint4 raw = *(const uint4*)&g_xl16[soff + ch0];
                float2 f0 = __half22float2(*(__half2*)&raw.x);
                float2 f1 = __half22float2(*(__half2*)&raw.y);
                float2 f2 = __half22float2(*(__half2*)&raw.z);
                float2 f3 = __half22float2(*(__half2*)&raw.w);
                xa = make_float4(f0.x, f0.y, f1.x, f1.y);
                xb = make_float4(f2.x, f2.y, f3.x, f3.y);
            } else {
                const float* xp = &g_xl32[soff];
                xa = *(const float4*)(xp + l16 * 4);       // plane A
                xb = *(const float4*)(xp + 64 + l16 * 4);  // plane B
            }
            float e, pa = 0.f, pb = 0.f;
            e = xa.x + xrA.x; e = fmaxf(e, 0.2f * e); pa = fmaf(e, attA.x, pa);
            e = xa.y + xrA.y; e = fmaxf(e, 0.2f * e); pa = fmaf(e, attA.y, pa);
            e = xa.z + xrA.z; e = fmaxf(e, 0.2f * e); pa = fmaf(e, attA.z, pa);
            e = xa.w + xrA.w; e = fmaxf(e, 0.2f * e); pa = fmaf(e, attA.w, pa);
            e = xb.x + xrB.x; e = fmaxf(e, 0.2f * e); pb = fmaf(e, attB.x, pb);
            e = xb.y + xrB.y; e = fmaxf(e, 0.2f * e); pb = fmaf(e, attB.y, pb);
            e = xb.z + xrB.z; e = fmaxf(e, 0.2f * e); pb = fmaf(e, attB.z, pb);
            e = xb.w + xrB.w; e = fmaxf(e, 0.2f * e); pb = fmaf(e, attB.w, pb);
            float p = pa + pb;
            p += __shfl_xor_sync(FULLMASK, p, 4);
            p += __shfl_xor_sync(FULLMASK, p, 2);
            p += __shfl_xor_sync(FULLMASK, p, 1);
            float w = valid ? ex2(fminf(p, 126.f)) : 0.f;
            z += w;
            accA.x += w * xa.x; accA.y += w * xa.y;
            accA.z += w * xa.z; accA.w += w * xa.w;
            accB.x += w * xb.x; accB.y += w * xb.y;
            accB.z += w * xb.z; accB.w += w * xb.w;
        }
    }

    z += __shfl_xor_sync(FULLMASK, z, 16);
    accA.x += __shfl_xor_sync(FULLMASK, accA.x, 16);
    accA.y += __shfl_xor_sync(FULLMASK, accA.y, 16);
    accA.z += __shfl_xor_sync(FULLMASK, accA.z, 16);
    accA.w += __shfl_xor_sync(FULLMASK, accA.w, 16);
    accB.x += __shfl_xor_sync(FULLMASK, accB.x, 16);
    accB.y += __shfl_xor_sync(FULLMASK, accB.y, 16);
    accB.z += __shfl_xor_sync(FULLMASK, accB.z, 16);
    accB.w += __shfl_xor_sync(FULLMASK, accB.w, 16);
    float inv = 1.f / z;
    float rA0 = accA.x * inv, rA1 = accA.y * inv, rA2 = accA.z * inv, rA3 = accA.w * inv;
    float rB0 = accB.x * inv, rB1 = accB.y * inv, rB2 = accB.z * inv, rB3 = accB.w * inv;
    float o0 = 0.5f * (rA0 + __shfl_xor_sync(FULLMASK, rA0, 8));
    float o1 = 0.5f * (rA1 + __shfl_xor_sync(FULLMASK, rA1, 8));
    float o2 = 0.5f * (rA2 + __shfl_xor_sync(FULLMASK, rA2, 8));
    float o3 = 0.5f * (rA3 + __shfl_xor_sync(FULLMASK, rA3, 8));
    float o4 = 0.5f * (rB0 + __shfl_xor_sync(FULLMASK, rB0, 8));
    float o5 = 0.5f * (rB1 + __shfl_xor_sync(FULLMASK, rB1, 8));
    float o6 = 0.5f * (rB2 + __shfl_xor_sync(FULLMASK, rB2, 8));
    float o7 = 0.5f * (rB3 + __shfl_xor_sync(FULLMASK, rB3, 8));

    if (half == 0 && l16 < 8) {
        float4 bbA = *(const float4*)&bias[ch0];
        float4 bbB = *(const float4*)&bias[ch0 + 4];
        o0 += bbA.x; o1 += bbA.y; o2 += bbA.z; o3 += bbA.w;
        o4 += bbB.x; o5 += bbB.y; o6 += bbB.z; o7 += bbB.w;
        *(float4*)&g_y[(size_t)v * FF + ch0] = make_float4(o0, o1, o2, o3);
        *(float4*)&g_y[(size_t)v * FF + ch0 + 4] = make_float4(o4, o5, o6, o7);
        atomicAdd(&sS[ch0 + 0], o0); atomicAdd(&sS[FF + ch0 + 0], o0 * o0);
        atomicAdd(&sS[ch0 + 1], o1); atomicAdd(&sS[FF + ch0 + 1], o1 * o1);
        atomicAdd(&sS[ch0 + 2], o2); atomicAdd(&sS[FF + ch0 + 2], o2 * o2);
        atomicAdd(&sS[ch0 + 3], o3); atomicAdd(&sS[FF + ch0 + 3], o3 * o3);
        atomicAdd(&sS[ch0 + 4], o4); atomicAdd(&sS[FF + ch0 + 4], o4 * o4);
        atomicAdd(&sS[ch0 + 5], o5); atomicAdd(&sS[FF + ch0 + 5], o5 * o5);
        atomicAdd(&sS[ch0 + 6], o6); atomicAdd(&sS[FF + ch0 + 6], o6 * o6);
        atomicAdd(&sS[ch0 + 7], o7); atomicAdd(&sS[FF + ch0 + 7], o7 * o7);
    }
    __syncthreads();
    if (tid < 2 * FF) atomicAdd(&st[tid], sS[tid]);
}

// ---------------- final norm -> d_out, float4 ----------------
__global__ void k_norm(const float* __restrict__ st, const float* __restrict__ gw,
                       const float* __restrict__ gb, const float* __restrict__ gm,
                       float* __restrict__ out) {
    __shared__ float sA[64], sB[64];
    int tid = threadIdx.x;
    if (tid < 64) {
        const float invN = 1.f / (float)NN;
        float mu = st[tid] * invN;
        float ey2 = st[FF + tid] * invN;
        float gmc = gm[tid];
        float var = ey2 - 2.f * gmc * mu * mu + gmc * gmc * mu * mu;
        float al = gw[tid] * rsqrtf(var + 1e-5f);
        sA[tid] = al;
        sB[tid] = gb[tid] - al * gmc * mu;
    }
    __syncthreads();
    int idx = blockIdx.x * blockDim.x + tid;
    if (idx >= NN * FF / 4) return;
    int c = (idx * 4) & 63;
    float4 y = *(const float4*)&g_y[idx * 4];
    float4 o;
    o.x = fmaxf(sA[c + 0] * y.x + sB[c + 0], 0.f);
    o.y = fmaxf(sA[c + 1] * y.y + sB[c + 1], 0.f);
    o.z = fmaxf(sA[c + 2] * y.z + sB[c + 2], 0.f);
    o.w = fmaxf(sA[c + 3] * y.w + sB[c + 3], 0.f);
    *(float4*)&out[idx * 4] = o;
}

// ---------------- launch ----------------
extern "C" void kernel_launch(void* const* d_in, const int* in_sizes, int n_in,
                              void* d_out, int out_size) {
    const float* x = (const float*)d_in[0];
    const int* ei = (const int*)d_in[1];
    const float* P[3][7];
    for (int l = 0; l < 3; l++)
        for (int j = 0; j < 7; j++)
            P[l][j] = (const float*)d_in[2 + l * 7 + j];
    // j: 0 Wl, 1 Wr, 2 att, 3 b, 4 gw, 5 gb, 6 gm

    static float* s_stats_base = nullptr;
    static cudaStream_t s2 = nullptr;
    static cudaEvent_t evFork = nullptr, evJoin = nullptr;
    if (!s_stats_base) {
        void* p = nullptr;
        cudaGetSymbolAddress(&p, g_stats);
        s_stats_base = (float*)p;
        cudaStreamCreateWithFlags(&s2, cudaStreamNonBlocking);
        cudaEventCreateWithFlags(&evFork, cudaEventDisableTiming);
        cudaEventCreateWithFlags(&evJoin, cudaEventDisableTiming);
    }
    float* st0 = s_stats_base;
    float* st1 = s_stats_base + 2 * FF;
    float* st2 = s_stats_base + 4 * FF;

    dim3 ggrid((NN + 63) / 64, 2);
    int eblocks = (NN + 15) / 16;  // 3125

    // fork: gemmA on s2 concurrent with CSR build on main stream   (launch #1)
    cudaEventRecord(evFork, 0);
    cudaStreamWaitEvent(s2, evFork, 0);
    k_gemmA<<<ggrid, 256, 0, s2>>>(x, P[0][0], P[0][1]);
    cudaEventRecord(evJoin, s2);

    k_zero<<<(NN + 255) / 256, 256>>>();                 // #2
    k_csrall<<<NBLK, 1024>>>(ei);                        // #3

    cudaStreamWaitEvent(0, evJoin, 0);

    // layer 1 (fp32 quad-interleaved gather)            // #4 <- ncu window
    k_edge<false><<<eblocks, 512>>>(P[0][2], P[0][3], st0);
    // layer 2 (fp16 gather)
    k_gemmB<<<ggrid, 256>>>(P[1][0], P[1][1], st0, P[0][4], P[0][5], P[0][6]);
    k_edge<true><<<eblocks, 512>>>(P[1][2], P[1][3], st1);
    // layer 3 (fp16 gather)
    k_gemmB<<<ggrid, 256>>>(P[2][0], P[2][1], st1, P[1][4], P[1][5], P[1][6]);
    k_edge<true><<<eblocks, 512>>>(P[2][2], P[2][3], st2);
    // final norm
    k_norm<<<(NN * FF / 4 + 255) / 256, 256>>>(st2, P[2][4], P[2][5], P[2][6],
                                               (float*)d_out);
}

// round 12
// speedup vs baseline: 1.1463x; 1.1463x over previous
#include <cuda_runtime.h>
#include <cuda_fp16.h>
#include <math_constants.h>

#define NN 50000
#define EE 800000
#define ETOT (EE + NN)
#define HC 128
#define FF 64
#define FULLMASK 0xffffffffu
#define NB 49     // ceil(NN/1024)
#define NBLK 148  // one block per SM -> co-resident

typedef unsigned long long ull;

// ---------------- device scratch (static, no allocs) ----------------
__device__ int g_deg[NN];
__device__ int g_cur[NN];
__device__ int g_off[NN + 1];
__device__ int g_bsum[64];
__device__ int g_bars[4];
__device__ int g_srcs[ETOT];                // stores src<<7 (row element offset)
__device__ float g_xl32[(size_t)NN * HC];   // fp32, quad-interleaved (layer 1)
__device__ __half g_xl16[(size_t)NN * HC];  // fp16 gathered operand (layers 2,3)
__device__ float g_xr[(size_t)NN * HC];
__device__ float g_y[(size_t)NN * FF];
__device__ float g_stats[3][2 * FF];

// ---------------- zero (deg + stats + barriers) ----------------
__global__ void k_zero() {
    int i = blockIdx.x * blockDim.x + threadIdx.x;
    if (i < NN) g_deg[i] = 0;
    if (i < 3 * 2 * FF) ((float*)g_stats)[i] = 0.f;
    if (i < 4) g_bars[i] = 0;
}

// ---------------- persistent CSR kernel: hist + scan + scatter ----------------
__device__ __forceinline__ void gridbar(int k) {
    __threadfence();
    __syncthreads();
    if (threadIdx.x == 0) {
        atomicAdd(&g_bars[k], 1);
        while (*(volatile int*)&g_bars[k] < NBLK) { }
    }
    __syncthreads();
}

__global__ __launch_bounds__(1024) void k_csrall(const int* __restrict__ ei) {
    __shared__ int wsum[32];
    __shared__ int sh[64];
    int tid = threadIdx.x;
    int lane = tid & 31, wid = tid >> 5;
    int gtid = blockIdx.x * 1024 + tid;
    const int nthreads = NBLK * 1024;

    // P1: degree histogram (int4-vectorized)
    for (int t = gtid; t < EE / 4; t += nthreads) {
        int4 d4 = ((const int4*)(ei + EE))[t];
        atomicAdd(&g_deg[d4.x], 1);
        atomicAdd(&g_deg[d4.y], 1);
        atomicAdd(&g_deg[d4.z], 1);
        atomicAdd(&g_deg[d4.w], 1);
    }
    gridbar(0);

    // P2: per-1024-tile local inclusive scan (blocks 0..NB-1)
    int incl = 0, v = 0;
    int gi = blockIdx.x * 1024 + tid;
    if (blockIdx.x < NB) {
        v = (gi < NN) ? (g_deg[gi] + 1) : 0;  // +1 = self-loop
        int s = v;
#pragma unroll
        for (int d = 1; d < 32; d <<= 1) {
            int t = __shfl_up_sync(FULLMASK, s, d);
            if (lane >= d) s += t;
        }
        if (lane == 31) wsum[wid] = s;
        __syncthreads();
        if (wid == 0) {
            int w = wsum[lane];
#pragma unroll
            for (int d = 1; d < 32; d <<= 1) {
                int t = __shfl_up_sync(FULLMASK, w, d);
                if (lane >= d) w += t;
            }
            wsum[lane] = w;
        }
        __syncthreads();
        incl = s + (wid ? wsum[wid - 1] : 0);
        if (tid == 1023) g_bsum[blockIdx.x] = incl;
    }
    gridbar(1);

    // P3: every tile-block scans the NB block sums itself, then fixes its tile
    if (blockIdx.x < NB) {
        if (tid < 64) sh[tid] = (tid < NB) ? __ldcg(&g_bsum[tid]) : 0;
        __syncthreads();
        if (tid < 32) {
            int sa = sh[tid];
#pragma unroll
            for (int d = 1; d < 32; d <<= 1) {
                int t = __shfl_up_sync(FULLMASK, sa, d);
                if (lane >= d) sa += t;
            }
            int ta = __shfl_sync(FULLMASK, sa, 31);
            int sb = sh[tid + 32];
#pragma unroll
            for (int d = 1; d < 32; d <<= 1) {
                int t = __shfl_up_sync(FULLMASK, sb, d);
                if (lane >= d) sb += t;
            }
            sh[tid] = sa;
            sh[tid + 32] = sb + ta;
        }
        __syncthreads();
        int pre = blockIdx.x ? sh[blockIdx.x - 1] : 0;
        if (gi < NN) {
            int off = incl + pre;
            g_off[gi + 1] = off;
            g_cur[gi] = off - v;
        }
        if (gi == 0) g_off[0] = 0;
    }
    gridbar(2);

    // P4: scatter (int4-vectorized edges + self-loop tail); store src<<7
    for (int t = gtid; t < EE / 4 + NN; t += nthreads) {
        if (t < EE / 4) {
            int4 s4 = ((const int4*)ei)[t];
            int4 d4 = ((const int4*)(ei + EE))[t];
            g_srcs[atomicAdd(&g_cur[d4.x], 1)] = s4.x << 7;
            g_srcs[atomicAdd(&g_cur[d4.y], 1)] = s4.y << 7;
            g_srcs[atomicAdd(&g_cur[d4.z], 1)] = s4.z << 7;
            g_srcs[atomicAdd(&g_cur[d4.w], 1)] = s4.w << 7;
        } else {
            int n = t - EE / 4;
            g_srcs[atomicAdd(&g_cur[n], 1)] = n << 7;
        }
    }
}

// ---------------- GEMM layer 1 (K=3): xl->fp32 quad-interleaved, xr->fp32 ----------------
__global__ void k_gemmA(const float* __restrict__ X,
                        const float* __restrict__ Wl,
                        const float* __restrict__ Wr) {
    __shared__ float sW[3][HC];
    __shared__ float sX[64][3];
    const float* W = (blockIdx.y == 0) ? Wl : Wr;
    int tid = threadIdx.x;
    int row0 = blockIdx.x * 64;

    for (int idx = tid; idx < 3 * HC; idx += 256)
        sW[idx / HC][idx % HC] = W[idx];
    for (int idx = tid; idx < 64 * 3; idx += 256) {
        int r = idx / 3, k = idx % 3;
        sX[r][k] = (row0 + r < NN) ? X[(size_t)(row0 + r) * 3 + k] : 0.f;
    }
    __syncthreads();

    int tx = tid & 31, ty = tid >> 5;
    float4 acc[8];
#pragma unroll
    for (int i = 0; i < 8; i++) acc[i] = make_float4(0.f, 0.f, 0.f, 0.f);
#pragma unroll
    for (int k = 0; k < 3; k++) {
        float4 b = *(const float4*)&sW[k][tx * 4];
#pragma unroll
        for (int i = 0; i < 8; i++) {
            float a = sX[ty * 8 + i][k];
            acc[i].x += a * b.x;
            acc[i].y += a * b.y;
            acc[i].z += a * b.z;
            acc[i].w += a * b.w;
        }
    }
    int scol = (blockIdx.y == 0) ? ((tx & 1) * 64 + (tx >> 1) * 4) : (tx * 4);
    float* out = (blockIdx.y == 0) ? g_xl32 : g_xr;
#pragma unroll
    for (int i = 0; i < 8; i++) {
        int r = row0 + ty * 8 + i;
        if (r < NN) *(float4*)&out[(size_t)r * HC + scol] = acc[i];
    }
}

// ---------------- GEMM layers 2,3 (K=64): xl->fp16, xr->fp32, fused norm+relu ----------------
#define SXIDX(k, r) (((k) << 6) + ((((((r) >> 1) ^ ((k) & 31))) << 1) | ((r) & 1)))

__global__ __launch_bounds__(256) void k_gemmB(
    const float* __restrict__ Wl, const float* __restrict__ Wr,
    const float* __restrict__ st, const float* __restrict__ gw,
    const float* __restrict__ gb, const float* __restrict__ gm) {
    __shared__ float sW[64 * HC];
    __shared__ float sX[64 * 64];
    __shared__ float sA[64], sB[64];
    int tid = threadIdx.x;
    const float* W = (blockIdx.y == 0) ? Wl : Wr;
    int row0 = blockIdx.x * 64;

    if (tid < 64) {
        const float invN = 1.f / (float)NN;
        float mu = st[tid] * invN;
        float ey2 = st[FF + tid] * invN;
        float gmc = gm[tid];
        float var = ey2 - 2.f * gmc * mu * mu + gmc * gmc * mu * mu;
        float al = gw[tid] * rsqrtf(var + 1e-5f);
        sA[tid] = al;
        sB[tid] = gb[tid] - al * gmc * mu;
    }
    for (int idx = tid; idx < 64 * HC; idx += 256) sW[idx] = W[idx];
    __syncthreads();
    for (int idx = tid; idx < 64 * 64; idx += 256) {
        int r = idx >> 6, k = idx & 63;
        float v = 0.f;
        if (row0 + r < NN) {
            float y = g_y[(size_t)(row0 + r) * FF + k];
            v = fmaxf(sA[k] * y + sB[k], 0.f);
        }
        sX[SXIDX(k, r)] = v;
    }
    __syncthreads();

    int tx = tid & 31, ty = tid >> 5;
    unsigned long long acc[4][4];
#pragma unroll
    for (int i = 0; i < 4; i++)
#pragma unroll
        for (int c = 0; c < 4; c++) acc[i][c] = 0ull;

#pragma unroll 4
    for (int k = 0; k < 64; k++) {
        float4 b4 = *(const float4*)&sW[k * HC + tx * 4];
        unsigned long long bs0, bs1, bs2, bs3;
        asm("mov.b64 %0, {%1,%1};" : "=l"(bs0) : "f"(b4.x));
        asm("mov.b64 %0, {%1,%1};" : "=l"(bs1) : "f"(b4.y));
        asm("mov.b64 %0, {%1,%1};" : "=l"(bs2) : "f"(b4.z));
        asm("mov.b64 %0, {%1,%1};" : "=l"(bs3) : "f"(b4.w));
#pragma unroll
        for (int i = 0; i < 4; i++) {
            unsigned long long a =
                *(const unsigned long long*)&sX[SXIDX(k, ty * 8 + 2 * i)];
            asm("fma.rn.f32x2 %0, %1, %2, %0;" : "+l"(acc[i][0]) : "l"(a), "l"(bs0));
            asm("fma.rn.f32x2 %0, %1, %2, %0;" : "+l"(acc[i][1]) : "l"(a), "l"(bs1));
            asm("fma.rn.f32x2 %0, %1, %2, %0;" : "+l"(acc[i][2]) : "l"(a), "l"(bs2));
            asm("fma.rn.f32x2 %0, %1, %2, %0;" : "+l"(acc[i][3]) : "l"(a), "l"(bs3));
        }
    }

#pragma unroll
    for (int i = 0; i < 4; i++) {
        int r = row0 + ty * 8 + 2 * i;
        float lo[4], hi[4];
#pragma unroll
        for (int c = 0; c < 4; c++)
            asm("mov.b64 {%0,%1}, %2;" : "=f"(lo[c]), "=f"(hi[c]) : "l"(acc[i][c]));
        if (blockIdx.y == 0) {
            if (r < NN) {
                *(__half2*)&g_xl16[(size_t)r * HC + tx * 4] = __floats2half2_rn(lo[0], lo[1]);
                *(__half2*)&g_xl16[(size_t)r * HC + tx * 4 + 2] = __floats2half2_rn(lo[2], lo[3]);
            }
            if (r + 1 < NN) {
                *(__half2*)&g_xl16[(size_t)(r + 1) * HC + tx * 4] = __floats2half2_rn(hi[0], hi[1]);
                *(__half2*)&g_xl16[(size_t)(r + 1) * HC + tx * 4 + 2] = __floats2half2_rn(hi[2], hi[3]);
            }
        } else {
            if (r < NN)
                *(float4*)&g_xr[(size_t)r * HC + tx * 4] = make_float4(lo[0], lo[1], lo[2], lo[3]);
            if (r + 1 < NN)
                *(float4*)&g_xr[(size_t)(r + 1) * HC + tx * 4] = make_float4(hi[0], hi[1], hi[2], hi[3]);
        }
    }
}

// ---------------- edge kernel: warp per node, 2 edges/iter, packed f32x2 math ----------------
__device__ __forceinline__ float ex2(float x) {
    float r;
    asm("ex2.approx.f32 %0, %1;" : "=f"(r) : "f"(x));
    return r;
}

__device__ __forceinline__ ull packf2(float lo, float hi) {
    ull r;
    asm("mov.b64 %0, {%1,%2};" : "=l"(r) : "f"(lo), "f"(hi));
    return r;
}

template <bool HALFXL>
__global__ __launch_bounds__(512) void k_edge(const float* __restrict__ att,
                                              const float* __restrict__ bias,
                                              float* __restrict__ st) {
    __shared__ float sS[2 * FF];
    int tid = threadIdx.x;
    if (tid < 2 * FF) sS[tid] = 0.f;
    __syncthreads();

    int warp = tid >> 5;
    int lane = tid & 31;
    int v = blockIdx.x * 16 + warp;
    int half = lane >> 4;
    int l16 = lane & 15;
    int ch0 = l16 * 8;

    const float LOG2E = 1.4426950408889634f;
    const ull ABSMASK = 0x7FFFFFFF7FFFFFFFull;
    const unsigned u04 = __float_as_uint(0.4f);
    const unsigned u06 = __float_as_uint(0.6f);
    const ull C04 = ((ull)u04 << 32) | u04;
    const ull C06 = ((ull)u06 << 32) | u06;

    ull at[4], xr[4];
    {
        float4 a0 = *(const float4*)&att[ch0];
        float4 a1 = *(const float4*)&att[ch0 + 4];
        at[0] = packf2(a0.x * LOG2E, a0.y * LOG2E);
        at[1] = packf2(a0.z * LOG2E, a0.w * LOG2E);
        at[2] = packf2(a1.x * LOG2E, a1.y * LOG2E);
        at[3] = packf2(a1.z * LOG2E, a1.w * LOG2E);
        float4 r0 = *(const float4*)&g_xr[(size_t)v * HC + ch0];
        float4 r1 = *(const float4*)&g_xr[(size_t)v * HC + ch0 + 4];
        xr[0] = packf2(r0.x, r0.y);
        xr[1] = packf2(r0.z, r0.w);
        xr[2] = packf2(r1.x, r1.y);
        xr[3] = packf2(r1.z, r1.w);
    }

    float z = 0.f;
    ull acc[4];
#pragma unroll
    for (int i = 0; i < 4; i++) acc[i] = 0ull;

#define PAIR(T)                                                                \
    {                                                                          \
        int eidx = 2 * (T) + half;                                             \
        bool valid = eidx < cnt;                                               \
        int soff = __shfl_sync(FULLMASK, sb, eidx);                            \
        ull xv[4];                                                             \
        if (HALFXL) {                                                          \
            uint4 raw = *(const uint4*)&g_xl16[soff + ch0];                    \
            float2 f0 = __half22float2(*(__half2*)&raw.x);                     \
            float2 f1 = __half22float2(*(__half2*)&raw.y);                     \
            float2 f2 = __half22float2(*(__half2*)&raw.z);                     \
            float2 f3 = __half22float2(*(__half2*)&raw.w);                     \
            xv[0] = packf2(f0.x, f0.y); xv[1] = packf2(f1.x, f1.y);            \
            xv[2] = packf2(f2.x, f2.y); xv[3] = packf2(f3.x, f3.y);            \
        } else {                                                               \
            ulonglong2 A = *(const ulonglong2*)&g_xl32[soff + l16 * 4];        \
            ulonglong2 B = *(const ulonglong2*)&g_xl32[soff + 64 + l16 * 4];   \
            xv[0] = A.x; xv[1] = A.y; xv[2] = B.x; xv[3] = B.y;                \
        }                                                                      \
        ull pd = 0ull;                                                         \
        _Pragma("unroll")                                                      \
        for (int i = 0; i < 4; i++) {                                          \
            ull e, ab, m, l;                                                   \
            asm("add.rn.f32x2 %0, %1, %2;" : "=l"(e) : "l"(xv[i]), "l"(xr[i]));\
            asm("and.b64 %0, %1, %2;" : "=l"(ab) : "l"(e), "l"(ABSMASK));      \
            asm("mul.rn.f32x2 %0, %1, %2;" : "=l"(m) : "l"(ab), "l"(C04));     \
            asm("fma.rn.f32x2 %0, %1, %2, %3;" : "=l"(l) : "l"(e), "l"(C06), "l"(m)); \
            asm("fma.rn.f32x2 %0, %1, %2, %0;" : "+l"(pd) : "l"(l), "l"(at[i]));\
        }                                                                      \
        float plo, phi;                                                        \
        asm("mov.b64 {%0,%1}, %2;" : "=f"(plo), "=f"(phi) : "l"(pd));          \
        float p = plo + phi;                                                   \
        p += __shfl_xor_sync(FULLMASK, p, 4);                                  \
        p += __shfl_xor_sync(FULLMASK, p, 2);                                  \
        p += __shfl_xor_sync(FULLMASK, p, 1);                                  \
        float w = valid ? ex2(fminf(p, 126.f)) : 0.f;                          \
        z += w;                                                                \
        ull w2;                                                                \
        asm("mov.b64 %0, {%1,%1};" : "=l"(w2) : "f"(w));                       \
        _Pragma("unroll")                                                      \
        for (int i = 0; i < 4; i++)                                            \
            asm("fma.rn.f32x2 %0, %1, %2, %0;" : "+l"(acc[i]) : "l"(w2), "l"(xv[i])); \
    }

    int beg = g_off[v], end = g_off[v + 1];
    for (int base = beg; base < end; base += 32) {
        int idx = base + lane;
        int sb = (idx < end) ? g_srcs[idx] : 0;  // src<<7
        int cnt = min(32, end - base);
        int pairs = (cnt + 1) >> 1;
        int t = 0;
        for (; t + 2 <= pairs; t += 2) { PAIR(t) PAIR(t + 1) }
        if (t < pairs) PAIR(t)
    }
#undef PAIR

    // unpack accumulators
    float a[8];
#pragma unroll
    for (int i = 0; i < 4; i++)
        asm("mov.b64 {%0,%1}, %2;" : "=f"(a[2 * i]), "=f"(a[2 * i + 1]) : "l"(acc[i]));

    z += __shfl_xor_sync(FULLMASK, z, 16);
#pragma unroll
    for (int i = 0; i < 8; i++) a[i] += __shfl_xor_sync(FULLMASK, a[i], 16);
    float inv = 1.f / z;
#pragma unroll
    for (int i = 0; i < 8; i++) {
        a[i] *= inv;
        a[i] = 0.5f * (a[i] + __shfl_xor_sync(FULLMASK, a[i], 8));
    }

    if (half == 0 && l16 < 8) {
        float4 bbA = *(const float4*)&bias[ch0];
        float4 bbB = *(const float4*)&bias[ch0 + 4];
        float o0 = a[0] + bbA.x, o1 = a[1] + bbA.y;
        float o2 = a[2] + bbA.z, o3 = a[3] + bbA.w;
        float o4 = a[4] + bbB.x, o5 = a[5] + bbB.y;
        float o6 = a[6] + bbB.z, o7 = a[7] + bbB.w;
        *(float4*)&g_y[(size_t)v * FF + ch0] = make_float4(o0, o1, o2, o3);
        *(float4*)&g_y[(size_t)v * FF + ch0 + 4] = make_float4(o4, o5, o6, o7);
        atomicAdd(&sS[ch0 + 0], o0); atomicAdd(&sS[FF + ch0 + 0], o0 * o0);
        atomicAdd(&sS[ch0 + 1], o1); atomicAdd(&sS[FF + ch0 + 1], o1 * o1);
        atomicAdd(&sS[ch0 + 2], o2); atomicAdd(&sS[FF + ch0 + 2], o2 * o2);
        atomicAdd(&sS[ch0 + 3], o3); atomicAdd(&sS[FF + ch0 + 3], o3 * o3);
        atomicAdd(&sS[ch0 + 4], o4); atomicAdd(&sS[FF + ch0 + 4], o4 * o4);
        atomicAdd(&sS[ch0 + 5], o5); atomicAdd(&sS[FF + ch0 + 5], o5 * o5);
        atomicAdd(&sS[ch0 + 6], o6); atomicAdd(&sS[FF + ch0 + 6], o6 * o6);
        atomicAdd(&sS[ch0 + 7], o7); atomicAdd(&sS[FF + ch0 + 7], o7 * o7);
    }
    __syncthreads();
    if (tid < 2 * FF) atomicAdd(&st[tid], sS[tid]);
}

// ---------------- final norm -> d_out, float4 ----------------
__global__ void k_norm(const float* __restrict__ st, const float* __restrict__ gw,
                       const float* __restrict__ gb, const float* __restrict__ gm,
                       float* __restrict__ out) {
    __shared__ float sA[64], sB[64];
    int tid = threadIdx.x;
    if (tid < 64) {
        const float invN = 1.f / (float)NN;
        float mu = st[tid] * invN;
        float ey2 = st[FF + tid] * invN;
        float gmc = gm[tid];
        float var = ey2 - 2.f * gmc * mu * mu + gmc * gmc * mu * mu;
        float al = gw[tid] * rsqrtf(var + 1e-5f);
        sA[tid] = al;
        sB[tid] = gb[tid] - al * gmc * mu;
    }
    __syncthreads();
    int idx = blockIdx.x * blockDim.x + tid;
    if (idx >= NN * FF / 4) return;
    int c = (idx * 4) & 63;
    float4 y = *(const float4*)&g_y[idx * 4];
    float4 o;
    o.x = fmaxf(sA[c + 0] * y.x + sB[c + 0], 0.f);
    o.y = fmaxf(sA[c + 1] * y.y + sB[c + 1], 0.f);
    o.z = fmaxf(sA[c + 2] * y.z + sB[c + 2], 0.f);
    o.w = fmaxf(sA[c + 3] * y.w + sB[c + 3], 0.f);
    *(float4*)&out[idx * 4] = o;
}

// ---------------- launch ----------------
extern "C" void kernel_launch(void* const* d_in, const int* in_sizes, int n_in,
                              void* d_out, int out_size) {
    const float* x = (const float*)d_in[0];
    const int* ei = (const int*)d_in[1];
    const float* P[3][7];
    for (int l = 0; l < 3; l++)
        for (int j = 0; j < 7; j++)
            P[l][j] = (const float*)d_in[2 + l * 7 + j];
    // j: 0 Wl, 1 Wr, 2 att, 3 b, 4 gw, 5 gb, 6 gm

    static float* s_stats_base = nullptr;
    static cudaStream_t s2 = nullptr;
    static cudaEvent_t evFork = nullptr, evJoin = nullptr;
    if (!s_stats_base) {
        void* p = nullptr;
        cudaGetSymbolAddress(&p, g_stats);
        s_stats_base = (float*)p;
        cudaStreamCreateWithFlags(&s2, cudaStreamNonBlocking);
        cudaEventCreateWithFlags(&evFork, cudaEventDisableTiming);
        cudaEventCreateWithFlags(&evJoin, cudaEventDisableTiming);
    }
    float* st0 = s_stats_base;
    float* st1 = s_stats_base + 2 * FF;
    float* st2 = s_stats_base + 4 * FF;

    dim3 ggrid((NN + 63) / 64, 2);
    int eblocks = (NN + 15) / 16;  // 3125

    // fork: gemmA on s2 concurrent with CSR build on main stream   (launch #1)
    cudaEventRecord(evFork, 0);
    cudaStreamWaitEvent(s2, evFork, 0);
    k_gemmA<<<ggrid, 256, 0, s2>>>(x, P[0][0], P[0][1]);
    cudaEventRecord(evJoin, s2);

    k_zero<<<(NN + 255) / 256, 256>>>();                 // #2
    k_csrall<<<NBLK, 1024>>>(ei);                        // #3

    cudaStreamWaitEvent(0, evJoin, 0);

    // layer 1 (fp32 quad-interleaved gather)            // #4 <- ncu window
    k_edge<false><<<eblocks, 512>>>(P[0][2], P[0][3], st0);
    // layer 2 (fp16 gather)
    k_gemmB<<<ggrid, 256>>>(P[1][0], P[1][1], st0, P[0][4], P[0][5], P[0][6]);
    k_edge<true><<<eblocks, 512>>>(P[1][2], P[1][3], st1);
    // layer 3 (fp16 gather)
    k_gemmB<<<ggrid, 256>>>(P[2][0], P[2][1], st1, P[1][4], P[1][5], P[1][6]);
    k_edge<true><<<eblocks, 512>>>(P[2][2], P[2][3], st2);
    // final norm
    k_norm<<<(NN * FF / 4 + 255) / 256, 256>>>(st2, P[2][4], P[2][5], P[2][6],
                                               (float*)d_out);
}

// round 15
// speedup vs baseline: 1.1677x; 1.0187x over previous
#include <cuda_runtime.h>
#include <cuda_fp16.h>
#include <math_constants.h>

#define NN 50000
#define EE 800000
#define ETOT (EE + NN)
#define HC 128
#define FF 64
#define FULLMASK 0xffffffffu
#define NB 49     // ceil(NN/1024)
#define NBLK 148  // one block per SM -> co-resident

typedef unsigned long long ull;

// ---------------- device scratch (static, no allocs) ----------------
__device__ int g_deg[NN];
__device__ int g_cur[NN];
__device__ int g_off[NN + 1];
__device__ int g_bsum[64];
__device__ int g_bars[4];
__device__ int g_srcs[ETOT];                // stores src<<7 (row element offset)
__device__ __half g_xl16[(size_t)NN * HC];  // fp16 gathered operand (all layers)
__device__ float g_xr[(size_t)NN * HC];
__device__ float g_y[(size_t)NN * FF];
__device__ float g_stats[3][2 * FF];

// ---------------- zero (deg + stats + barriers) ----------------
__global__ void k_zero() {
    int i = blockIdx.x * blockDim.x + threadIdx.x;
    if (i < NN) g_deg[i] = 0;
    if (i < 3 * 2 * FF) ((float*)g_stats)[i] = 0.f;
    if (i < 4) g_bars[i] = 0;
}

// ---------------- persistent CSR kernel: hist + scan + scatter ----------------
__device__ __forceinline__ void gridbar(int k) {
    __threadfence();
    __syncthreads();
    if (threadIdx.x == 0) {
        atomicAdd(&g_bars[k], 1);
        while (*(volatile int*)&g_bars[k] < NBLK) { }
    }
    __syncthreads();
}

__global__ __launch_bounds__(1024) void k_csrall(const int* __restrict__ ei) {
    __shared__ int wsum[32];
    __shared__ int sh[64];
    int tid = threadIdx.x;
    int lane = tid & 31, wid = tid >> 5;
    int gtid = blockIdx.x * 1024 + tid;
    const int nthreads = NBLK * 1024;

    // P1: degree histogram (int4-vectorized)
    for (int t = gtid; t < EE / 4; t += nthreads) {
        int4 d4 = ((const int4*)(ei + EE))[t];
        atomicAdd(&g_deg[d4.x], 1);
        atomicAdd(&g_deg[d4.y], 1);
        atomicAdd(&g_deg[d4.z], 1);
        atomicAdd(&g_deg[d4.w], 1);
    }
    gridbar(0);

    // P2: per-1024-tile local inclusive scan (blocks 0..NB-1)
    int incl = 0, v = 0;
    int gi = blockIdx.x * 1024 + tid;
    if (blockIdx.x < NB) {
        v = (gi < NN) ? (g_deg[gi] + 1) : 0;  // +1 = self-loop
        int s = v;
#pragma unroll
        for (int d = 1; d < 32; d <<= 1) {
            int t = __shfl_up_sync(FULLMASK, s, d);
            if (lane >= d) s += t;
        }
        if (lane == 31) wsum[wid] = s;
        __syncthreads();
        if (wid == 0) {
            int w = wsum[lane];
#pragma unroll
            for (int d = 1; d < 32; d <<= 1) {
                int t = __shfl_up_sync(FULLMASK, w, d);
                if (lane >= d) w += t;
            }
            wsum[lane] = w;
        }
        __syncthreads();
        incl = s + (wid ? wsum[wid - 1] : 0);
        if (tid == 1023) g_bsum[blockIdx.x] = incl;
    }
    gridbar(1);

    // P3: every tile-block scans the NB block sums itself, then fixes its tile
    if (blockIdx.x < NB) {
        if (tid < 64) sh[tid] = (tid < NB) ? __ldcg(&g_bsum[tid]) : 0;
        __syncthreads();
        if (tid < 32) {
            int sa = sh[tid];
#pragma unroll
            for (int d = 1; d < 32; d <<= 1) {
                int t = __shfl_up_sync(FULLMASK, sa, d);
                if (lane >= d) sa += t;
            }
            int ta = __shfl_sync(FULLMASK, sa, 31);
            int sb = sh[tid + 32];
#pragma unroll
            for (int d = 1; d < 32; d <<= 1) {
                int t = __shfl_up_sync(FULLMASK, sb, d);
                if (lane >= d) sb += t;
            }
            sh[tid] = sa;
            sh[tid + 32] = sb + ta;
        }
        __syncthreads();
        int pre = blockIdx.x ? sh[blockIdx.x - 1] : 0;
        if (gi < NN) {
            int off = incl + pre;
            g_off[gi + 1] = off;
            g_cur[gi] = off - v;
        }
        if (gi == 0) g_off[0] = 0;
    }
    gridbar(2);

    // P4: scatter (int4-vectorized edges + self-loop tail); store src<<7
    for (int t = gtid; t < EE / 4 + NN; t += nthreads) {
        if (t < EE / 4) {
            int4 s4 = ((const int4*)ei)[t];
            int4 d4 = ((const int4*)(ei + EE))[t];
            g_srcs[atomicAdd(&g_cur[d4.x], 1)] = s4.x << 7;
            g_srcs[atomicAdd(&g_cur[d4.y], 1)] = s4.y << 7;
            g_srcs[atomicAdd(&g_cur[d4.z], 1)] = s4.z << 7;
            g_srcs[atomicAdd(&g_cur[d4.w], 1)] = s4.w << 7;
        } else {
            int n = t - EE / 4;
            g_srcs[atomicAdd(&g_cur[n], 1)] = n << 7;
        }
    }
}

// ---------------- GEMM layer 1 (K=3): xl->fp16, xr->fp32 ----------------
__global__ void k_gemmA(const float* __restrict__ X,
                        const float* __restrict__ Wl,
                        const float* __restrict__ Wr) {
    __shared__ float sW[3][HC];
    __shared__ float sX[64][3];
    const float* W = (blockIdx.y == 0) ? Wl : Wr;
    int tid = threadIdx.x;
    int row0 = blockIdx.x * 64;

    for (int idx = tid; idx < 3 * HC; idx += 256)
        sW[idx / HC][idx % HC] = W[idx];
    for (int idx = tid; idx < 64 * 3; idx += 256) {
        int r = idx / 3, k = idx % 3;
        sX[r][k] = (row0 + r < NN) ? X[(size_t)(row0 + r) * 3 + k] : 0.f;
    }
    __syncthreads();

    int tx = tid & 31, ty = tid >> 5;
    float4 acc[8];
#pragma unroll
    for (int i = 0; i < 8; i++) acc[i] = make_float4(0.f, 0.f, 0.f, 0.f);
#pragma unroll
    for (int k = 0; k < 3; k++) {
        float4 b = *(const float4*)&sW[k][tx * 4];
#pragma unroll
        for (int i = 0; i < 8; i++) {
            float a = sX[ty * 8 + i][k];
            acc[i].x += a * b.x;
            acc[i].y += a * b.y;
            acc[i].z += a * b.z;
            acc[i].w += a * b.w;
        }
    }
#pragma unroll
    for (int i = 0; i < 8; i++) {
        int r = row0 + ty * 8 + i;
        if (r >= NN) continue;
        if (blockIdx.y == 0) {
            *(__half2*)&g_xl16[(size_t)r * HC + tx * 4] = __floats2half2_rn(acc[i].x, acc[i].y);
            *(__half2*)&g_xl16[(size_t)r * HC + tx * 4 + 2] = __floats2half2_rn(acc[i].z, acc[i].w);
        } else {
            *(float4*)&g_xr[(size_t)r * HC + tx * 4] = acc[i];
        }
    }
}

// ---------------- GEMM layers 2,3 (K=64): xl->fp16, xr->fp32, fused norm+relu ----------------
#define SXIDX(k, r) (((k) << 6) + ((((((r) >> 1) ^ ((k) & 31))) << 1) | ((r) & 1)))

__global__ __launch_bounds__(256) void k_gemmB(
    const float* __restrict__ Wl, const float* __restrict__ Wr,
    const float* __restrict__ st, const float* __restrict__ gw,
    const float* __restrict__ gb, const float* __restrict__ gm) {
    __shared__ float sW[64 * HC];
    __shared__ float sX[64 * 64];
    __shared__ float sA[64], sB[64];
    int tid = threadIdx.x;
    const float* W = (blockIdx.y == 0) ? Wl : Wr;
    int row0 = blockIdx.x * 64;

    if (tid < 64) {
        const float invN = 1.f / (float)NN;
        float mu = st[tid] * invN;
        float ey2 = st[FF + tid] * invN;
        float gmc = gm[tid];
        float var = ey2 - 2.f * gmc * mu * mu + gmc * gmc * mu * mu;
        float al = gw[tid] * rsqrtf(var + 1e-5f);
        sA[tid] = al;
        sB[tid] = gb[tid] - al * gmc * mu;
    }
    for (int idx = tid; idx < 64 * HC; idx += 256) sW[idx] = W[idx];
    __syncthreads();
    for (int idx = tid; idx < 64 * 64; idx += 256) {
        int r = idx >> 6, k = idx & 63;
        float v = 0.f;
        if (row0 + r < NN) {
            float y = g_y[(size_t)(row0 + r) * FF + k];
            v = fmaxf(sA[k] * y + sB[k], 0.f);
        }
        sX[SXIDX(k, r)] = v;
    }
    __syncthreads();

    int tx = tid & 31, ty = tid >> 5;
    unsigned long long acc[4][4];
#pragma unroll
    for (int i = 0; i < 4; i++)
#pragma unroll
        for (int c = 0; c < 4; c++) acc[i][c] = 0ull;

#pragma unroll 4
    for (int k = 0; k < 64; k++) {
        float4 b4 = *(const float4*)&sW[k * HC + tx * 4];
        unsigned long long bs0, bs1, bs2, bs3;
        asm("mov.b64 %0, {%1,%1};" : "=l"(bs0) : "f"(b4.x));
        asm("mov.b64 %0, {%1,%1};" : "=l"(bs1) : "f"(b4.y));
        asm("mov.b64 %0, {%1,%1};" : "=l"(bs2) : "f"(b4.z));
        asm("mov.b64 %0, {%1,%1};" : "=l"(bs3) : "f"(b4.w));
#pragma unroll
        for (int i = 0; i < 4; i++) {
            unsigned long long a =
                *(const unsigned long long*)&sX[SXIDX(k, ty * 8 + 2 * i)];
            asm("fma.rn.f32x2 %0, %1, %2, %0;" : "+l"(acc[i][0]) : "l"(a), "l"(bs0));
            asm("fma.rn.f32x2 %0, %1, %2, %0;" : "+l"(acc[i][1]) : "l"(a), "l"(bs1));
            asm("fma.rn.f32x2 %0, %1, %2, %0;" : "+l"(acc[i][2]) : "l"(a), "l"(bs2));
            asm("fma.rn.f32x2 %0, %1, %2, %0;" : "+l"(acc[i][3]) : "l"(a), "l"(bs3));
        }
    }

#pragma unroll
    for (int i = 0; i < 4; i++) {
        int r = row0 + ty * 8 + 2 * i;
        float lo[4], hi[4];
#pragma unroll
        for (int c = 0; c < 4; c++)
            asm("mov.b64 {%0,%1}, %2;" : "=f"(lo[c]), "=f"(hi[c]) : "l"(acc[i][c]));
        if (blockIdx.y == 0) {
            if (r < NN) {
                *(__half2*)&g_xl16[(size_t)r * HC + tx * 4] = __floats2half2_rn(lo[0], lo[1]);
                *(__half2*)&g_xl16[(size_t)r * HC + tx * 4 + 2] = __floats2half2_rn(lo[2], lo[3]);
            }
            if (r + 1 < NN) {
                *(__half2*)&g_xl16[(size_t)(r + 1) * HC + tx * 4] = __floats2half2_rn(hi[0], hi[1]);
                *(__half2*)&g_xl16[(size_t)(r + 1) * HC + tx * 4 + 2] = __floats2half2_rn(hi[2], hi[3]);
            }
        } else {
            if (r < NN)
                *(float4*)&g_xr[(size_t)r * HC + tx * 4] = make_float4(lo[0], lo[1], lo[2], lo[3]);
            if (r + 1 < NN)
                *(float4*)&g_xr[(size_t)(r + 1) * HC + tx * 4] = make_float4(hi[0], hi[1], hi[2], hi[3]);
        }
    }
}

// ---------------- edge kernel: warp per node, 2 edges/iter, fp16 gather ----------------
__device__ __forceinline__ float ex2(float x) {
    float r;
    asm("ex2.approx.f32 %0, %1;" : "=f"(r) : "f"(x));
    return r;
}

__global__ __launch_bounds__(512) void k_edge(const float* __restrict__ att,
                                              const float* __restrict__ bias,
                                              float* __restrict__ st) {
    __shared__ float sS[2 * FF];
    int tid = threadIdx.x;
    if (tid < 2 * FF) sS[tid] = 0.f;
    __syncthreads();

    int warp = tid >> 5;
    int lane = tid & 31;
    int v = blockIdx.x * 16 + warp;
    int half = lane >> 4;
    int l16 = lane & 15;
    int ch0 = l16 * 8;

    const float LOG2E = 1.4426950408889634f;
    float4 attA = *(const float4*)&att[ch0];
    float4 attB = *(const float4*)&att[ch0 + 4];
    attA.x *= LOG2E; attA.y *= LOG2E; attA.z *= LOG2E; attA.w *= LOG2E;
    attB.x *= LOG2E; attB.y *= LOG2E; attB.z *= LOG2E; attB.w *= LOG2E;
    float4 xrA = *(const float4*)&g_xr[(size_t)v * HC + ch0];
    float4 xrB = *(const float4*)&g_xr[(size_t)v * HC + ch0 + 4];

    float z = 0.f;
    float4 accA = make_float4(0.f, 0.f, 0.f, 0.f);
    float4 accB = make_float4(0.f, 0.f, 0.f, 0.f);

#define PAIR(T)                                                                \
    {                                                                          \
        int eidx = 2 * (T) + half;                                             \
        bool valid = eidx < cnt;                                               \
        int soff = __shfl_sync(FULLMASK, sb, eidx);                            \
        uint4 raw = *(const uint4*)&g_xl16[soff + ch0];                        \
        float2 f0 = __half22float2(*(__half2*)&raw.x);                         \
        float2 f1 = __half22float2(*(__half2*)&raw.y);                         \
        float2 f2 = __half22float2(*(__half2*)&raw.z);                         \
        float2 f3 = __half22float2(*(__half2*)&raw.w);                         \
        float4 xa = make_float4(f0.x, f0.y, f1.x, f1.y);                       \
        float4 xb = make_float4(f2.x, f2.y, f3.x, f3.y);                       \
        float e, pa = 0.f, pb = 0.f;                                           \
        e = xa.x + xrA.x; e = fmaxf(e, 0.2f * e); pa = fmaf(e, attA.x, pa);    \
        e = xa.y + xrA.y; e = fmaxf(e, 0.2f * e); pa = fmaf(e, attA.y, pa);    \
        e = xa.z + xrA.z; e = fmaxf(e, 0.2f * e); pa = fmaf(e, attA.z, pa);    \
        e = xa.w + xrA.w; e = fmaxf(e, 0.2f * e); pa = fmaf(e, attA.w, pa);    \
        e = xb.x + xrB.x; e = fmaxf(e, 0.2f * e); pb = fmaf(e, attB.x, pb);    \
        e = xb.y + xrB.y; e = fmaxf(e, 0.2f * e); pb = fmaf(e, attB.y, pb);    \
        e = xb.z + xrB.z; e = fmaxf(e, 0.2f * e); pb = fmaf(e, attB.z, pb);    \
        e = xb.w + xrB.w; e = fmaxf(e, 0.2f * e); pb = fmaf(e, attB.w, pb);    \
        float p = pa + pb;                                                     \
        p += __shfl_xor_sync(FULLMASK, p, 4);                                  \
        p += __shfl_xor_sync(FULLMASK, p, 2);                                  \
        p += __shfl_xor_sync(FULLMASK, p, 1);                                  \
        float w = valid ? ex2(fminf(p, 126.f)) : 0.f;                          \
        z += w;                                                                \
        accA.x += w * xa.x; accA.y += w * xa.y;                                \
        accA.z += w * xa.z; accA.w += w * xa.w;                                \
        accB.x += w * xb.x; accB.y += w * xb.y;                                \
        accB.z += w * xb.z; accB.w += w * xb.w;                                \
    }

    int beg = g_off[v], end = g_off[v + 1];
    for (int base = beg; base < end; base += 32) {
        int idx = base + lane;
        int sb = (idx < end) ? g_srcs[idx] : 0;  // src<<7
        int cnt = min(32, end - base);
        int pairs = (cnt + 1) >> 1;
        int t = 0;
        for (; t + 2 <= pairs; t += 2) { PAIR(t) PAIR(t + 1) }
        if (t < pairs) PAIR(t)
    }
#undef PAIR

    z += __shfl_xor_sync(FULLMASK, z, 16);
    accA.x += __shfl_xor_sync(FULLMASK, accA.x, 16);
    accA.y += __shfl_xor_sync(FULLMASK, accA.y, 16);
    accA.z += __shfl_xor_sync(FULLMASK, accA.z, 16);
    accA.w += __shfl_xor_sync(FULLMASK, accA.w, 16);
    accB.x += __shfl_xor_sync(FULLMASK, accB.x, 16);
    accB.y += __shfl_xor_sync(FULLMASK, accB.y, 16);
    accB.z += __shfl_xor_sync(FULLMASK, accB.z, 16);
    accB.w += __shfl_xor_sync(FULLMASK, accB.w, 16);
    float inv = 1.f / z;
    float rA0 = accA.x * inv, rA1 = accA.y * inv, rA2 = accA.z * inv, rA3 = accA.w * inv;
    float rB0 = accB.x * inv, rB1 = accB.y * inv, rB2 = accB.z * inv, rB3 = accB.w * inv;
    float o0 = 0.5f * (rA0 + __shfl_xor_sync(FULLMASK, rA0, 8));
    float o1 = 0.5f * (rA1 + __shfl_xor_sync(FULLMASK, rA1, 8));
    float o2 = 0.5f * (rA2 + __shfl_xor_sync(FULLMASK, rA2, 8));
    float o3 = 0.5f * (rA3 + __shfl_xor_sync(FULLMASK, rA3, 8));
    float o4 = 0.5f * (rB0 + __shfl_xor_sync(FULLMASK, rB0, 8));
    float o5 = 0.5f * (rB1 + __shfl_xor_sync(FULLMASK, rB1, 8));
    float o6 = 0.5f * (rB2 + __shfl_xor_sync(FULLMASK, rB2, 8));
    float o7 = 0.5f * (rB3 + __shfl_xor_sync(FULLMASK, rB3, 8));

    if (half == 0 && l16 < 8) {
        float4 bbA = *(const float4*)&bias[ch0];
        float4 bbB = *(const float4*)&bias[ch0 + 4];
        o0 += bbA.x; o1 += bbA.y; o2 += bbA.z; o3 += bbA.w;
        o4 += bbB.x; o5 += bbB.y; o6 += bbB.z; o7 += bbB.w;
        *(float4*)&g_y[(size_t)v * FF + ch0] = make_float4(o0, o1, o2, o3);
        *(float4*)&g_y[(size_t)v * FF + ch0 + 4] = make_float4(o4, o5, o6, o7);
        atomicAdd(&sS[ch0 + 0], o0); atomicAdd(&sS[FF + ch0 + 0], o0 * o0);
        atomicAdd(&sS[ch0 + 1], o1); atomicAdd(&sS[FF + ch0 + 1], o1 * o1);
        atomicAdd(&sS[ch0 + 2], o2); atomicAdd(&sS[FF + ch0 + 2], o2 * o2);
        atomicAdd(&sS[ch0 + 3], o3); atomicAdd(&sS[FF + ch0 + 3], o3 * o3);
        atomicAdd(&sS[ch0 + 4], o4); atomicAdd(&sS[FF + ch0 + 4], o4 * o4);
        atomicAdd(&sS[ch0 + 5], o5); atomicAdd(&sS[FF + ch0 + 5], o5 * o5);
        atomicAdd(&sS[ch0 + 6], o6); atomicAdd(&sS[FF + ch0 + 6], o6 * o6);
        atomicAdd(&sS[ch0 + 7], o7); atomicAdd(&sS[FF + ch0 + 7], o7 * o7);
    }
    __syncthreads();
    if (tid < 2 * FF) atomicAdd(&st[tid], sS[tid]);
}

// ---------------- final norm -> d_out, float4 ----------------
__global__ void k_norm(const float* __restrict__ st, const float* __restrict__ gw,
                       const float* __restrict__ gb, const float* __restrict__ gm,
                       float* __restrict__ out) {
    __shared__ float sA[64], sB[64];
    int tid = threadIdx.x;
    if (tid < 64) {
        const float invN = 1.f / (float)NN;
        float mu = st[tid] * invN;
        float ey2 = st[FF + tid] * invN;
        float gmc = gm[tid];
        float var = ey2 - 2.f * gmc * mu * mu + gmc * gmc * mu * mu;
        float al = gw[tid] * rsqrtf(var + 1e-5f);
        sA[tid] = al;
        sB[tid] = gb[tid] - al * gmc * mu;
    }
    __syncthreads();
    int idx = blockIdx.x * blockDim.x + tid;
    if (idx >= NN * FF / 4) return;
    int c = (idx * 4) & 63;
    float4 y = *(const float4*)&g_y[idx * 4];
    float4 o;
    o.x = fmaxf(sA[c + 0] * y.x + sB[c + 0], 0.f);
    o.y = fmaxf(sA[c + 1] * y.y + sB[c + 1], 0.f);
    o.z = fmaxf(sA[c + 2] * y.z + sB[c + 2], 0.f);
    o.w = fmaxf(sA[c + 3] * y.w + sB[c + 3], 0.f);
    *(float4*)&out[idx * 4] = o;
}

// ---------------- launch ----------------
extern "C" void kernel_launch(void* const* d_in, const int* in_sizes, int n_in,
                              void* d_out, int out_size) {
    const float* x = (const float*)d_in[0];
    const int* ei = (const int*)d_in[1];
    const float* P[3][7];
    for (int l = 0; l < 3; l++)
        for (int j = 0; j < 7; j++)
            P[l][j] = (const float*)d_in[2 + l * 7 + j];
    // j: 0 Wl, 1 Wr, 2 att, 3 b, 4 gw, 5 gb, 6 gm

    static float* s_stats_base = nullptr;
    static cudaStream_t s2 = nullptr;
    static cudaEvent_t evFork = nullptr, evJoin = nullptr;
    if (!s_stats_base) {
        void* p = nullptr;
        cudaGetSymbolAddress(&p, g_stats);
        s_stats_base = (float*)p;
        cudaStreamCreateWithFlags(&s2, cudaStreamNonBlocking);
        cudaEventCreateWithFlags(&evFork, cudaEventDisableTiming);
        cudaEventCreateWithFlags(&evJoin, cudaEventDisableTiming);
    }
    float* st0 = s_stats_base;
    float* st1 = s_stats_base + 2 * FF;
    float* st2 = s_stats_base + 4 * FF;

    dim3 ggrid((NN + 63) / 64, 2);
    int eblocks = (NN + 15) / 16;  // 3125

    // fork: gemmA on s2 concurrent with CSR build on main stream   (launch #1)
    cudaEventRecord(evFork, 0);
    cudaStreamWaitEvent(s2, evFork, 0);
    k_gemmA<<<ggrid, 256, 0, s2>>>(x, P[0][0], P[0][1]);
    cudaEventRecord(evJoin, s2);

    k_zero<<<(NN + 255) / 256, 256>>>();                 // #2
    k_csrall<<<NBLK, 1024>>>(ei);                        // #3

    cudaStreamWaitEvent(0, evJoin, 0);

    // layer 1 (fp16 gather)                             // #4 <- ncu window
    k_edge<<<eblocks, 512>>>(P[0][2], P[0][3], st0);
    // layer 2 (fp16 gather)
    k_gemmB<<<ggrid, 256>>>(P[1][0], P[1][1], st0, P[0][4], P[0][5], P[0][6]);
    k_edge<<<eblocks, 512>>>(P[1][2], P[1][3], st1);
    // layer 3 (fp16 gather)
    k_gemmB<<<ggrid, 256>>>(P[2][0], P[2][1], st1, P[1][4], P[1][5], P[1][6]);
    k_edge<<<eblocks, 512>>>(P[2][2], P[2][3], st2);
    // final norm
    k_norm<<<(NN * FF / 4 + 255) / 256, 256>>>(st2, P[2][4], P[2][5], P[2][6],
                                               (float*)d_out);
}

// round 16
// speedup vs baseline: 1.2250x; 1.0491x over previous
#include <cuda_runtime.h>
#include <cuda_fp16.h>
#include <math_constants.h>

#define NN 50000
#define EE 800000
#define ETOT (EE + NN)
#define HC 128
#define FF 64
#define FULLMASK 0xffffffffu
#define NB 49     // ceil(NN/1024)
#define NBLK 148  // csr: one block per SM -> co-resident
#define EBLK 296  // edge: persistent, 2 blocks per SM

typedef unsigned long long ull;

// ---------------- device scratch (static, no allocs) ----------------
__device__ int g_deg[NN];
__device__ int g_cur[NN];
__device__ int2 g_span[NN];                 // {beg, end} into g_srcs
__device__ int g_bsum[64];
__device__ int g_bars[4];
__device__ int g_srcs[ETOT];                // stores src<<7 (row element offset)
__device__ __half g_xl16[(size_t)NN * HC];  // fp16 gathered operand (all layers)
__device__ float g_xr[(size_t)NN * HC];
__device__ float g_y[(size_t)NN * FF];
__device__ float g_stats[3][2 * FF];

// ---------------- zero (deg + stats + barriers) ----------------
__global__ void k_zero() {
    int i = blockIdx.x * blockDim.x + threadIdx.x;
    if (i < NN) g_deg[i] = 0;
    if (i < 3 * 2 * FF) ((float*)g_stats)[i] = 0.f;
    if (i < 4) g_bars[i] = 0;
}

// ---------------- persistent CSR kernel: hist + scan + scatter ----------------
__device__ __forceinline__ void gridbar(int k) {
    __threadfence();
    __syncthreads();
    if (threadIdx.x == 0) {
        atomicAdd(&g_bars[k], 1);
        while (*(volatile int*)&g_bars[k] < NBLK) { }
    }
    __syncthreads();
}

__global__ __launch_bounds__(1024) void k_csrall(const int* __restrict__ ei) {
    __shared__ int wsum[32];
    __shared__ int sh[64];
    int tid = threadIdx.x;
    int lane = tid & 31, wid = tid >> 5;
    int gtid = blockIdx.x * 1024 + tid;
    const int nthreads = NBLK * 1024;

    // P1: degree histogram (int4-vectorized)
    for (int t = gtid; t < EE / 4; t += nthreads) {
        int4 d4 = ((const int4*)(ei + EE))[t];
        atomicAdd(&g_deg[d4.x], 1);
        atomicAdd(&g_deg[d4.y], 1);
        atomicAdd(&g_deg[d4.z], 1);
        atomicAdd(&g_deg[d4.w], 1);
    }
    gridbar(0);

    // P2: per-1024-tile local inclusive scan (blocks 0..NB-1)
    int incl = 0, v = 0;
    int gi = blockIdx.x * 1024 + tid;
    if (blockIdx.x < NB) {
        v = (gi < NN) ? (g_deg[gi] + 1) : 0;  // +1 = self-loop
        int s = v;
#pragma unroll
        for (int d = 1; d < 32; d <<= 1) {
            int t = __shfl_up_sync(FULLMASK, s, d);
            if (lane >= d) s += t;
        }
        if (lane == 31) wsum[wid] = s;
        __syncthreads();
        if (wid == 0) {
            int w = wsum[lane];
#pragma unroll
            for (int d = 1; d < 32; d <<= 1) {
                int t = __shfl_up_sync(FULLMASK, w, d);
                if (lane >= d) w += t;
            }
            wsum[lane] = w;
        }
        __syncthreads();
        incl = s + (wid ? wsum[wid - 1] : 0);
        if (tid == 1023) g_bsum[blockIdx.x] = incl;
    }
    gridbar(1);

    // P3: every tile-block scans the NB block sums itself, then fixes its tile
    if (blockIdx.x < NB) {
        if (tid < 64) sh[tid] = (tid < NB) ? __ldcg(&g_bsum[tid]) : 0;
        __syncthreads();
        if (tid < 32) {
            int sa = sh[tid];
#pragma unroll
            for (int d = 1; d < 32; d <<= 1) {
                int t = __shfl_up_sync(FULLMASK, sa, d);
                if (lane >= d) sa += t;
            }
            int ta = __shfl_sync(FULLMASK, sa, 31);
            int sb = sh[tid + 32];
#pragma unroll
            for (int d = 1; d < 32; d <<= 1) {
                int t = __shfl_up_sync(FULLMASK, sb, d);
                if (lane >= d) sb += t;
            }
            sh[tid] = sa;
            sh[tid + 32] = sb + ta;
        }
        __syncthreads();
        int pre = blockIdx.x ? sh[blockIdx.x - 1] : 0;
        if (gi < NN) {
            int off = incl + pre;
            g_span[gi] = make_int2(off - v, off);
            g_cur[gi] = off - v;
        }
    }
    gridbar(2);

    // P4: scatter (int4-vectorized edges + self-loop tail); store src<<7
    for (int t = gtid; t < EE / 4 + NN; t += nthreads) {
        if (t < EE / 4) {
            int4 s4 = ((const int4*)ei)[t];
            int4 d4 = ((const int4*)(ei + EE))[t];
            g_srcs[atomicAdd(&g_cur[d4.x], 1)] = s4.x << 7;
            g_srcs[atomicAdd(&g_cur[d4.y], 1)] = s4.y << 7;
            g_srcs[atomicAdd(&g_cur[d4.z], 1)] = s4.z << 7;
            g_srcs[atomicAdd(&g_cur[d4.w], 1)] = s4.w << 7;
        } else {
            int n = t - EE / 4;
            g_srcs[atomicAdd(&g_cur[n], 1)] = n << 7;
        }
    }
}

// ---------------- GEMM layer 1 (K=3): xl->fp16, xr->fp32 ----------------
__global__ void k_gemmA(const float* __restrict__ X,
                        const float* __restrict__ Wl,
                        const float* __restrict__ Wr) {
    __shared__ float sW[3][HC];
    __shared__ float sX[64][3];
    const float* W = (blockIdx.y == 0) ? Wl : Wr;
    int tid = threadIdx.x;
    int row0 = blockIdx.x * 64;

    for (int idx = tid; idx < 3 * HC; idx += 256)
        sW[idx / HC][idx % HC] = W[idx];
    for (int idx = tid; idx < 64 * 3; idx += 256) {
        int r = idx / 3, k = idx % 3;
        sX[r][k] = (row0 + r < NN) ? X[(size_t)(row0 + r) * 3 + k] : 0.f;
    }
    __syncthreads();

    int tx = tid & 31, ty = tid >> 5;
    float4 acc[8];
#pragma unroll
    for (int i = 0; i < 8; i++) acc[i] = make_float4(0.f, 0.f, 0.f, 0.f);
#pragma unroll
    for (int k = 0; k < 3; k++) {
        float4 b = *(const float4*)&sW[k][tx * 4];
#pragma unroll
        for (int i = 0; i < 8; i++) {
            float a = sX[ty * 8 + i][k];
            acc[i].x += a * b.x;
            acc[i].y += a * b.y;
            acc[i].z += a * b.z;
            acc[i].w += a * b.w;
        }
    }
#pragma unroll
    for (int i = 0; i < 8; i++) {
        int r = row0 + ty * 8 + i;
        if (r >= NN) continue;
        if (blockIdx.y == 0) {
            *(__half2*)&g_xl16[(size_t)r * HC + tx * 4] = __floats2half2_rn(acc[i].x, acc[i].y);
            *(__half2*)&g_xl16[(size_t)r * HC + tx * 4 + 2] = __floats2half2_rn(acc[i].z, acc[i].w);
        } else {
            *(float4*)&g_xr[(size_t)r * HC + tx * 4] = acc[i];
        }
    }
}

// ---------------- GEMM layers 2,3 (K=64): xl->fp16, xr->fp32, fused norm+relu ----------------
#define SXIDX(k, r) (((k) << 6) + ((((((r) >> 1) ^ ((k) & 31))) << 1) | ((r) & 1)))

__global__ __launch_bounds__(256) void k_gemmB(
    const float* __restrict__ Wl, const float* __restrict__ Wr,
    const float* __restrict__ st, const float* __restrict__ gw,
    const float* __restrict__ gb, const float* __restrict__ gm) {
    __shared__ float sW[64 * HC];
    __shared__ float sX[64 * 64];
    __shared__ float sA[64], sB[64];
    int tid = threadIdx.x;
    const float* W = (blockIdx.y == 0) ? Wl : Wr;
    int row0 = blockIdx.x * 64;

    if (tid < 64) {
        const float invN = 1.f / (float)NN;
        float mu = st[tid] * invN;
        float ey2 = st[FF + tid] * invN;
        float gmc = gm[tid];
        float var = ey2 - 2.f * gmc * mu * mu + gmc * gmc * mu * mu;
        float al = gw[tid] * rsqrtf(var + 1e-5f);
        sA[tid] = al;
        sB[tid] = gb[tid] - al * gmc * mu;
    }
    for (int idx = tid; idx < 64 * HC; idx += 256) sW[idx] = W[idx];
    __syncthreads();
    for (int idx = tid; idx < 64 * 64; idx += 256) {
        int r = idx >> 6, k = idx & 63;
        float v = 0.f;
        if (row0 + r < NN) {
            float y = g_y[(size_t)(row0 + r) * FF + k];
            v = fmaxf(sA[k] * y + sB[k], 0.f);
        }
        sX[SXIDX(k, r)] = v;
    }
    __syncthreads();

    int tx = tid & 31, ty = tid >> 5;
    unsigned long long acc[4][4];
#pragma unroll
    for (int i = 0; i < 4; i++)
#pragma unroll
        for (int c = 0; c < 4; c++) acc[i][c] = 0ull;

#pragma unroll 4
    for (int k = 0; k < 64; k++) {
        float4 b4 = *(const float4*)&sW[k * HC + tx * 4];
        unsigned long long bs0, bs1, bs2, bs3;
        asm("mov.b64 %0, {%1,%1};" : "=l"(bs0) : "f"(b4.x));
        asm("mov.b64 %0, {%1,%1};" : "=l"(bs1) : "f"(b4.y));
        asm("mov.b64 %0, {%1,%1};" : "=l"(bs2) : "f"(b4.z));
        asm("mov.b64 %0, {%1,%1};" : "=l"(bs3) : "f"(b4.w));
#pragma unroll
        for (int i = 0; i < 4; i++) {
            unsigned long long a =
                *(const unsigned long long*)&sX[SXIDX(k, ty * 8 + 2 * i)];
            asm("fma.rn.f32x2 %0, %1, %2, %0;" : "+l"(acc[i][0]) : "l"(a), "l"(bs0));
            asm("fma.rn.f32x2 %0, %1, %2, %0;" : "+l"(acc[i][1]) : "l"(a), "l"(bs1));
            asm("fma.rn.f32x2 %0, %1, %2, %0;" : "+l"(acc[i][2]) : "l"(a), "l"(bs2));
            asm("fma.rn.f32x2 %0, %1, %2, %0;" : "+l"(acc[i][3]) : "l"(a), "l"(bs3));
        }
    }

#pragma unroll
    for (int i = 0; i < 4; i++) {
        int r = row0 + ty * 8 + 2 * i;
        float lo[4], hi[4];
#pragma unroll
        for (int c = 0; c < 4; c++)
            asm("mov.b64 {%0,%1}, %2;" : "=f"(lo[c]), "=f"(hi[c]) : "l"(acc[i][c]));
        if (blockIdx.y == 0) {
            if (r < NN) {
                *(__half2*)&g_xl16[(size_t)r * HC + tx * 4] = __floats2half2_rn(lo[0], lo[1]);
                *(__half2*)&g_xl16[(size_t)r * HC + tx * 4 + 2] = __floats2half2_rn(lo[2], lo[3]);
            }
            if (r + 1 < NN) {
                *(__half2*)&g_xl16[(size_t)(r + 1) * HC + tx * 4] = __floats2half2_rn(hi[0], hi[1]);
                *(__half2*)&g_xl16[(size_t)(r + 1) * HC + tx * 4 + 2] = __floats2half2_rn(hi[2], hi[3]);
            }
        } else {
            if (r < NN)
                *(float4*)&g_xr[(size_t)r * HC + tx * 4] = make_float4(lo[0], lo[1], lo[2], lo[3]);
            if (r + 1 < NN)
                *(float4*)&g_xr[(size_t)(r + 1) * HC + tx * 4] = make_float4(hi[0], hi[1], hi[2], hi[3]);
        }
    }
}

// ---------------- edge kernel: persistent, multi-node warps, prefetch pipeline ----------------
__device__ __forceinline__ float ex2(float x) {
    float r;
    asm("ex2.approx.f32 %0, %1;" : "=f"(r) : "f"(x));
    return r;
}

__global__ __launch_bounds__(512, 2) void k_edge(const float* __restrict__ att,
                                                 const float* __restrict__ bias,
                                                 float* __restrict__ st) {
    __shared__ float sS[2 * FF];
    int tid = threadIdx.x;
    if (tid < 2 * FF) sS[tid] = 0.f;
    __syncthreads();

    int warp = tid >> 5;
    int lane = tid & 31;
    int half = lane >> 4;
    int l16 = lane & 15;
    int ch0 = l16 * 8;
    const int NW = EBLK * 16;  // 4736 warps
    int v = blockIdx.x * 16 + warp;

    const float LOG2E = 1.4426950408889634f;
    float4 attA = *(const float4*)&att[ch0];
    float4 attB = *(const float4*)&att[ch0 + 4];
    attA.x *= LOG2E; attA.y *= LOG2E; attA.z *= LOG2E; attA.w *= LOG2E;
    attB.x *= LOG2E; attB.y *= LOG2E; attB.z *= LOG2E; attB.w *= LOG2E;

    // pipeline prologue: first node's span + first srcs window
    int2 sp = g_span[v];
    int sb = (sp.x + lane < sp.y) ? g_srcs[sp.x + lane] : 0;

    for (;;) {
        int vn = v + NW;
        bool hn = vn < NN;
        int2 spn = make_int2(0, 0);
        if (hn) spn = g_span[vn];  // prefetch next span early

        float4 xrA = *(const float4*)&g_xr[(size_t)v * HC + ch0];
        float4 xrB = *(const float4*)&g_xr[(size_t)v * HC + ch0 + 4];

        float z = 0.f;
        float4 accA = make_float4(0.f, 0.f, 0.f, 0.f);
        float4 accB = make_float4(0.f, 0.f, 0.f, 0.f);

#define PAIR(T)                                                                \
    {                                                                          \
        int eidx = 2 * (T) + half;                                             \
        bool valid = eidx < cnt;                                               \
        int soff = __shfl_sync(FULLMASK, sb, eidx);                            \
        uint4 raw = *(const uint4*)&g_xl16[soff + ch0];                        \
        float2 f0 = __half22float2(*(__half2*)&raw.x);                         \
        float2 f1 = __half22float2(*(__half2*)&raw.y);                         \
        float2 f2 = __half22float2(*(__half2*)&raw.z);                         \
        float2 f3 = __half22float2(*(__half2*)&raw.w);                         \
        float4 xa = make_float4(f0.x, f0.y, f1.x, f1.y);                       \
        float4 xb = make_float4(f2.x, f2.y, f3.x, f3.y);                       \
        float e, pa = 0.f, pb = 0.f;                                           \
        e = xa.x + xrA.x; e = fmaxf(e, 0.2f * e); pa = fmaf(e, attA.x, pa);    \
        e = xa.y + xrA.y; e = fmaxf(e, 0.2f * e); pa = fmaf(e, attA.y, pa);    \
        e = xa.z + xrA.z; e = fmaxf(e, 0.2f * e); pa = fmaf(e, attA.z, pa);    \
        e = xa.w + xrA.w; e = fmaxf(e, 0.2f * e); pa = fmaf(e, attA.w, pa);    \
        e = xb.x + xrB.x; e = fmaxf(e, 0.2f * e); pb = fmaf(e, attB.x, pb);    \
        e = xb.y + xrB.y; e = fmaxf(e, 0.2f * e); pb = fmaf(e, attB.y, pb);    \
        e = xb.z + xrB.z; e = fmaxf(e, 0.2f * e); pb = fmaf(e, attB.z, pb);    \
        e = xb.w + xrB.w; e = fmaxf(e, 0.2f * e); pb = fmaf(e, attB.w, pb);    \
        float p = pa + pb;                                                     \
        p += __shfl_xor_sync(FULLMASK, p, 4);                                  \
        p += __shfl_xor_sync(FULLMASK, p, 2);                                  \
        p += __shfl_xor_sync(FULLMASK, p, 1);                                  \
        float w = valid ? ex2(fminf(p, 126.f)) : 0.f;                          \
        z += w;                                                                \
        accA.x += w * xa.x; accA.y += w * xa.y;                                \
        accA.z += w * xa.z; accA.w += w * xa.w;                                \
        accB.x += w * xb.x; accB.y += w * xb.y;                                \
        accB.z += w * xb.z; accB.w += w * xb.w;                                \
    }

        int base = sp.x, end = sp.y;
        while (base < end) {
            int cnt = min(32, end - base);
            int pairs = (cnt + 1) >> 1;
            int t = 0;
            for (; t + 2 <= pairs; t += 2) { PAIR(t) PAIR(t + 1) }
            if (t < pairs) PAIR(t)
            base += 32;
            if (base < end) sb = (base + lane < end) ? g_srcs[base + lane] : 0;
        }
#undef PAIR

        // prefetch next node's first srcs window (span has arrived); its
        // latency hides under the epilogue shuffle chain below
        int sbn = 0;
        if (hn) sbn = (spn.x + lane < spn.y) ? g_srcs[spn.x + lane] : 0;

        // ---- epilogue for node v ----
        z += __shfl_xor_sync(FULLMASK, z, 16);
        accA.x += __shfl_xor_sync(FULLMASK, accA.x, 16);
        accA.y += __shfl_xor_sync(FULLMASK, accA.y, 16);
        accA.z += __shfl_xor_sync(FULLMASK, accA.z, 16);
        accA.w += __shfl_xor_sync(FULLMASK, accA.w, 16);
        accB.x += __shfl_xor_sync(FULLMASK, accB.x, 16);
        accB.y += __shfl_xor_sync(FULLMASK, accB.y, 16);
        accB.z += __shfl_xor_sync(FULLMASK, accB.z, 16);
        accB.w += __shfl_xor_sync(FULLMASK, accB.w, 16);
        float inv = 1.f / z;
        float rA0 = accA.x * inv, rA1 = accA.y * inv, rA2 = accA.z * inv, rA3 = accA.w * inv;
        float rB0 = accB.x * inv, rB1 = accB.y * inv, rB2 = accB.z * inv, rB3 = accB.w * inv;
        float o0 = 0.5f * (rA0 + __shfl_xor_sync(FULLMASK, rA0, 8));
        float o1 = 0.5f * (rA1 + __shfl_xor_sync(FULLMASK, rA1, 8));
        float o2 = 0.5f * (rA2 + __shfl_xor_sync(FULLMASK, rA2, 8));
        float o3 = 0.5f * (rA3 + __shfl_xor_sync(FULLMASK, rA3, 8));
        float o4 = 0.5f * (rB0 + __shfl_xor_sync(FULLMASK, rB0, 8));
        float o5 = 0.5f * (rB1 + __shfl_xor_sync(FULLMASK, rB1, 8));
        float o6 = 0.5f * (rB2 + __shfl_xor_sync(FULLMASK, rB2, 8));
        float o7 = 0.5f * (rB3 + __shfl_xor_sync(FULLMASK, rB3, 8));

        if (half == 0 && l16 < 8) {
            float4 bbA = *(const float4*)&bias[ch0];
            float4 bbB = *(const float4*)&bias[ch0 + 4];
            o0 += bbA.x; o1 += bbA.y; o2 += bbA.z; o3 += bbA.w;
            o4 += bbB.x; o5 += bbB.y; o6 += bbB.z; o7 += bbB.w;
            *(float4*)&g_y[(size_t)v * FF + ch0] = make_float4(o0, o1, o2, o3);
            *(float4*)&g_y[(size_t)v * FF + ch0 + 4] = make_float4(o4, o5, o6, o7);
            atomicAdd(&sS[ch0 + 0], o0); atomicAdd(&sS[FF + ch0 + 0], o0 * o0);
            atomicAdd(&sS[ch0 + 1], o1); atomicAdd(&sS[FF + ch0 + 1], o1 * o1);
            atomicAdd(&sS[ch0 + 2], o2); atomicAdd(&sS[FF + ch0 + 2], o2 * o2);
            atomicAdd(&sS[ch0 + 3], o3); atomicAdd(&sS[FF + ch0 + 3], o3 * o3);
            atomicAdd(&sS[ch0 + 4], o4); atomicAdd(&sS[FF + ch0 + 4], o4 * o4);
            atomicAdd(&sS[ch0 + 5], o5); atomicAdd(&sS[FF + ch0 + 5], o5 * o5);
            atomicAdd(&sS[ch0 + 6], o6); atomicAdd(&sS[FF + ch0 + 6], o6 * o6);
            atomicAdd(&sS[ch0 + 7], o7); atomicAdd(&sS[FF + ch0 + 7], o7 * o7);
        }

        if (!hn) break;
        v = vn;
        sp = spn;
        sb = sbn;
    }

    __syncthreads();
    if (tid < 2 * FF) atomicAdd(&st[tid], sS[tid]);
}

// ---------------- final norm -> d_out, float4 ----------------
__global__ void k_norm(const float* __restrict__ st, const float* __restrict__ gw,
                       const float* __restrict__ gb, const float* __restrict__ gm,
                       float* __restrict__ out) {
    __shared__ float sA[64], sB[64];
    int tid = threadIdx.x;
    if (tid < 64) {
        const float invN = 1.f / (float)NN;
        float mu = st[tid] * invN;
        float ey2 = st[FF + tid] * invN;
        float gmc = gm[tid];
        float var = ey2 - 2.f * gmc * mu * mu + gmc * gmc * mu * mu;
        float al = gw[tid] * rsqrtf(var + 1e-5f);
        sA[tid] = al;
        sB[tid] = gb[tid] - al * gmc * mu;
    }
    __syncthreads();
    int idx = blockIdx.x * blockDim.x + tid;
    if (idx >= NN * FF / 4) return;
    int c = (idx * 4) & 63;
    float4 y = *(const float4*)&g_y[idx * 4];
    float4 o;
    o.x = fmaxf(sA[c + 0] * y.x + sB[c + 0], 0.f);
    o.y = fmaxf(sA[c + 1] * y.y + sB[c + 1], 0.f);
    o.z = fmaxf(sA[c + 2] * y.z + sB[c + 2], 0.f);
    o.w = fmaxf(sA[c + 3] * y.w + sB[c + 3], 0.f);
    *(float4*)&out[idx * 4] = o;
}

// ---------------- launch ----------------
extern "C" void kernel_launch(void* const* d_in, const int* in_sizes, int n_in,
                              void* d_out, int out_size) {
    const float* x = (const float*)d_in[0];
    const int* ei = (const int*)d_in[1];
    const float* P[3][7];
    for (int l = 0; l < 3; l++)
        for (int j = 0; j < 7; j++)
            P[l][j] = (const float*)d_in[2 + l * 7 + j];
    // j: 0 Wl, 1 Wr, 2 att, 3 b, 4 gw, 5 gb, 6 gm

    static float* s_stats_base = nullptr;
    static cudaStream_t s2 = nullptr;
    static cudaEvent_t evFork = nullptr, evJoin = nullptr;
    if (!s_stats_base) {
        void* p = nullptr;
        cudaGetSymbolAddress(&p, g_stats);
        s_stats_base = (float*)p;
        cudaStreamCreateWithFlags(&s2, cudaStreamNonBlocking);
        cudaEventCreateWithFlags(&evFork, cudaEventDisableTiming);
        cudaEventCreateWithFlags(&evJoin, cudaEventDisableTiming);
    }
    float* st0 = s_stats_base;
    float* st1 = s_stats_base + 2 * FF;
    float* st2 = s_stats_base + 4 * FF;

    dim3 ggrid((NN + 63) / 64, 2);

    // fork: gemmA on s2 concurrent with CSR build on main stream   (launch #1)
    cudaEventRecord(evFork, 0);
    cudaStreamWaitEvent(s2, evFork, 0);
    k_gemmA<<<ggrid, 256, 0, s2>>>(x, P[0][0], P[0][1]);
    cudaEventRecord(evJoin, s2);

    k_zero<<<(NN + 255) / 256, 256>>>();                 // #2
    k_csrall<<<NBLK, 1024>>>(ei);                        // #3

    cudaStreamWaitEvent(0, evJoin, 0);

    // layer 1 (fp16 gather)                             // #4 <- ncu window
    k_edge<<<EBLK, 512>>>(P[0][2], P[0][3], st0);
    // layer 2
    k_gemmB<<<ggrid, 256>>>(P[1][0], P[1][1], st0, P[0][4], P[0][5], P[0][6]);
    k_edge<<<EBLK, 512>>>(P[1][2], P[1][3], st1);
    // layer 3
    k_gemmB<<<ggrid, 256>>>(P[2][0], P[2][1], st1, P[1][4], P[1][5], P[1][6]);
    k_edge<<<EBLK, 512>>>(P[2][2], P[2][3], st2);
    // final norm
    k_norm<<<(NN * FF / 4 + 255) / 256, 256>>>(st2, P[2][4], P[2][5], P[2][6],
                                               (float*)d_out);
}